// round 1
// baseline (speedup 1.0000x reference)
#include <cuda_runtime.h>
#include <math.h>

#define Bb   8
#define Nn   4096
#define Dd   128
#define Pp   256
#define Kk   64
#define DFF  1024
#define BP   2048          // B*P patches
#define RT   131072        // BP*Kk point rows
#define EPSB 1e-5f

// ---------------- scratch (static device memory; no allocations) ----------------
__device__ int   d_fidx[BP];
__device__ int   d_gidx[RT];
__device__ float d_gxyz[RT * 3];
__device__ float d_pf[BP * Dd];
__device__ float d_ha[BP * DFF];
__device__ float d_hb[BP * DFF];
__device__ float d_coarse[BP * 48];
__device__ float d_base1[BP * DFF];
__device__ float d_h1[(size_t)RT * DFF];   // 512 MB
__device__ float d_h2[(size_t)RT * DFF];   // 512 MB
__device__ float d_fine[RT * 3];
__device__ float d_partial[BP];

// ---------------- FPS: one block per batch, sequential 255 argmax steps ----------------
__global__ void fps_kernel(const float* __restrict__ xyz) {
    int b = blockIdx.x;
    const float* X = xyz + (size_t)b * Nn * 3;
    int t = threadIdx.x;  // 256 threads, 16 points each (strided)

    float px[16], py[16], pz[16], md[16];
#pragma unroll
    for (int i = 0; i < 16; i++) {
        int n = i * 256 + t;
        px[i] = X[n * 3 + 0]; py[i] = X[n * 3 + 1]; pz[i] = X[n * 3 + 2];
        md[i] = 1e10f;
    }
    __shared__ float scx, scy, scz;
    __shared__ float wv[8];
    __shared__ int   wi[8];
    if (t == 0) { d_fidx[b * Pp] = 0; scx = X[0]; scy = X[1]; scz = X[2]; }
    __syncthreads();

    for (int step = 1; step < Pp; step++) {
        float cx = scx, cy = scy, cz = scz;
        float bv = -1e30f; int bn = 0;
#pragma unroll
        for (int i = 0; i < 16; i++) {
            // mirror reference arithmetic: (x-c)^2 summed, no FMA contraction
            float dx = __fadd_rn(px[i], -cx);
            float dy = __fadd_rn(py[i], -cy);
            float dz = __fadd_rn(pz[i], -cz);
            float d  = __fadd_rn(__fadd_rn(__fmul_rn(dx, dx), __fmul_rn(dy, dy)),
                                 __fmul_rn(dz, dz));
            float m = fminf(md[i], d);
            md[i] = m;
            if (m > bv) { bv = m; bn = i * 256 + t; }   // strict > keeps lowest n in-thread
        }
#pragma unroll
        for (int off = 16; off; off >>= 1) {
            float ov = __shfl_down_sync(0xffffffffu, bv, off);
            int   on = __shfl_down_sync(0xffffffffu, bn, off);
            if (ov > bv || (ov == bv && on < bn)) { bv = ov; bn = on; }
        }
        if ((t & 31) == 0) { wv[t >> 5] = bv; wi[t >> 5] = bn; }
        __syncthreads();
        if (t == 0) {
            float fv = wv[0]; int fn = wi[0];
#pragma unroll
            for (int w = 1; w < 8; w++)
                if (wv[w] > fv || (wv[w] == fv && wi[w] < fn)) { fv = wv[w]; fn = wi[w]; }
            d_fidx[b * Pp + step] = fn;
            scx = X[fn * 3 + 0]; scy = X[fn * 3 + 1]; scz = X[fn * 3 + 2];
        }
        __syncthreads();
    }
}

// ---------------- top-K (64 nearest of 4096) per patch + grouped_xyz_norm ----------------
__global__ void topk_kernel(const float* __restrict__ xyz) {
    int pp = blockIdx.x;          // 0..2047
    int b  = pp >> 8;
    const float* X = xyz + (size_t)b * Nn * 3;
    int t = threadIdx.x;          // 256

    __shared__ float sd[16 * 256];
    __shared__ float wv[8];
    __shared__ int   wi[8];
    __shared__ int   sel;

    int cI = d_fidx[pp];
    float cx = X[cI * 3 + 0], cy = X[cI * 3 + 1], cz = X[cI * 3 + 2];

    float mv = 1e30f; int mn = 0x7fffffff;
#pragma unroll
    for (int i = 0; i < 16; i++) {
        int n = i * 256 + t;
        float dx = X[n * 3 + 0] - cx, dy = X[n * 3 + 1] - cy, dz = X[n * 3 + 2] - cz;
        float d = dx * dx + dy * dy + dz * dz;
        sd[i * 256 + t] = d;
        if (d < mv) { mv = d; mn = n; }
    }

    for (int k = 0; k < Kk; k++) {
        float v = mv; int n = mn;
#pragma unroll
        for (int off = 16; off; off >>= 1) {
            float ov = __shfl_down_sync(0xffffffffu, v, off);
            int   on = __shfl_down_sync(0xffffffffu, n, off);
            if (ov < v || (ov == v && on < n)) { v = ov; n = on; }
        }
        if ((t & 31) == 0) { wv[t >> 5] = v; wi[t >> 5] = n; }
        __syncthreads();
        if (t == 0) {
            float fv = wv[0]; int fn = wi[0];
#pragma unroll
            for (int w = 1; w < 8; w++)
                if (wv[w] < fv || (wv[w] == fv && wi[w] < fn)) { fv = wv[w]; fn = wi[w]; }
            sel = fn;
            d_gidx[pp * Kk + k] = fn;
            d_gxyz[(pp * Kk + k) * 3 + 0] = X[fn * 3 + 0] - cx;
            d_gxyz[(pp * Kk + k) * 3 + 1] = X[fn * 3 + 1] - cy;
            d_gxyz[(pp * Kk + k) * 3 + 2] = X[fn * 3 + 2] - cz;
        }
        __syncthreads();
        int s = sel;
        if ((s & 255) == t) {           // winner thread removes + recomputes local min
            sd[(s >> 8) * 256 + t] = 1e30f;
            mv = 1e30f; mn = 0x7fffffff;
#pragma unroll
            for (int i = 0; i < 16; i++) {
                float d = sd[i * 256 + t];
                if (d < mv) { mv = d; mn = i * 256 + t; }
            }
        }
    }
}

// ---------------- patch feature: max over K neighbors ----------------
__global__ void pfeat_kernel(const float* __restrict__ feat) {
    int pp = blockIdx.x;          // 2048
    int b  = pp >> 8;
    int dch = threadIdx.x;        // 128
    const float* F = feat + (size_t)b * Nn * Dd;
    float mx = -1e30f;
#pragma unroll 4
    for (int k = 0; k < Kk; k++) {
        int n = d_gidx[pp * Kk + k];
        mx = fmaxf(mx, F[(size_t)n * Dd + dch]);
    }
    d_pf[pp * Dd + dch] = mx;
}

// ---------------- generic fp32 SGEMM 128x128x8, 256 thr, 8x8 microtile ----------------
// mode 0: +bias ; mode 1: +bias, relu ; mode 2: +bias, BN affine, relu
__global__ __launch_bounds__(256) void sgemm_kernel(
    const float* __restrict__ A, const float* __restrict__ B, const float* __restrict__ bias,
    const float* __restrict__ gg, const float* __restrict__ bb,
    const float* __restrict__ mm, const float* __restrict__ vv,
    float* __restrict__ C, int M, int N, int K, int mode)
{
    __shared__ float As[8][128];
    __shared__ float Bs[8][128];
    int tid = threadIdx.x;
    int bx = blockIdx.x, by = blockIdx.y;
    int tx = tid & 15, ty = tid >> 4;
    int row0 = by * 128, col0 = bx * 128;
    int ar = tid >> 1, ac = (tid & 1) * 4;
    int br = tid >> 5, bc = (tid & 31) * 4;
    const float* Ap = A + (size_t)(row0 + ar) * K + ac;
    const float* Bp = B + (size_t)br * N + col0 + bc;

    float acc[8][8];
#pragma unroll
    for (int i = 0; i < 8; i++)
#pragma unroll
        for (int j = 0; j < 8; j++) acc[i][j] = 0.f;

    for (int kt = 0; kt < K; kt += 8) {
        float4 a4 = *(const float4*)(Ap + kt);
        float4 b4 = *(const float4*)(Bp + (size_t)kt * N);
        __syncthreads();
        As[ac + 0][ar] = a4.x; As[ac + 1][ar] = a4.y;
        As[ac + 2][ar] = a4.z; As[ac + 3][ar] = a4.w;
        *(float4*)(&Bs[br][bc]) = b4;
        __syncthreads();
#pragma unroll
        for (int k = 0; k < 8; k++) {
            float a[8], bfr[8];
#pragma unroll
            for (int i = 0; i < 8; i++) a[i] = As[k][ty * 8 + i];
#pragma unroll
            for (int j = 0; j < 8; j++) bfr[j] = Bs[k][tx * 8 + j];
#pragma unroll
            for (int i = 0; i < 8; i++)
#pragma unroll
                for (int j = 0; j < 8; j++) acc[i][j] = fmaf(a[i], bfr[j], acc[i][j]);
        }
    }

#pragma unroll
    for (int j = 0; j < 8; j++) {
        int c = col0 + tx * 8 + j;
        float s = 1.f, tb = bias[c];
        if (mode == 2) {
            float sc = gg[c] * rsqrtf(vv[c] + EPSB);
            tb = (bias[c] - mm[c]) * sc + bb[c];
            s = sc;
        }
#pragma unroll
        for (int i = 0; i < 8; i++) {
            int r = row0 + ty * 8 + i;
            float x = acc[i][j] * s + tb;
            if (mode >= 1) x = fmaxf(x, 0.f);
            C[(size_t)r * N + c] = x;
        }
    }
}

// ---------------- MLP layer 3 (N=48): coarse = hb @ w3 + b3 ----------------
__global__ void mlp3_kernel(const float* __restrict__ w3, const float* __restrict__ b3) {
    int row = blockIdx.x;         // 2048
    __shared__ float a[1024];
    int t = threadIdx.x;          // 128
    for (int i = t; i < 1024; i += 128) a[i] = d_hb[(size_t)row * 1024 + i];
    __syncthreads();
    if (t < 48) {
        float s0 = 0.f, s1 = 0.f, s2 = 0.f, s3 = 0.f;
#pragma unroll 4
        for (int k = 0; k < 1024; k += 4) {
            s0 = fmaf(a[k + 0], w3[(k + 0) * 48 + t], s0);
            s1 = fmaf(a[k + 1], w3[(k + 1) * 48 + t], s1);
            s2 = fmaf(a[k + 2], w3[(k + 2) * 48 + t], s2);
            s3 = fmaf(a[k + 3], w3[(k + 3) * 48 + t], s3);
        }
        d_coarse[row * 48 + t] = ((s0 + s1) + (s2 + s3)) + b3[t];
    }
}

// ---------------- conv layer 1: h1 = relu(bn(base1 + seed/pts rank-1 terms)) ----------------
__global__ void conv1_kernel(const float* __restrict__ cw1, const float* __restrict__ g1,
                             const float* __restrict__ be1, const float* __restrict__ m1,
                             const float* __restrict__ v1) {
    int p = blockIdx.x;           // 2048 patches
    int t = threadIdx.x;          // 256
    float bs[4], c0[4], c1[4], c2[4], c3[4], c4[4], sc[4], tr[4];
#pragma unroll
    for (int q = 0; q < 4; q++) {
        int j = t + q * 256;
        bs[q] = d_base1[p * 1024 + j];
        c0[q] = cw1[128 * 1024 + j];
        c1[q] = cw1[129 * 1024 + j];
        c2[q] = cw1[130 * 1024 + j];
        c3[q] = cw1[131 * 1024 + j];
        c4[q] = cw1[132 * 1024 + j];
        float s = g1[j] * rsqrtf(v1[j] + EPSB);
        sc[q] = s;
        tr[q] = be1[j] - m1[j] * s;
    }
    for (int k = 0; k < 64; k++) {
        float sx = (k & 1) ? 0.05f : -0.05f;
        float sy = (k & 2) ? 0.05f : -0.05f;
        const float* cp = d_coarse + p * 48 + (k >> 2) * 3;
        float px = cp[0], py = cp[1], pz = cp[2];
        size_t rb = ((size_t)(p * 64 + k)) * 1024;
#pragma unroll
        for (int q = 0; q < 4; q++) {
            float tmp = bs[q] + sx * c0[q] + sy * c1[q] + px * c2[q] + py * c3[q] + pz * c4[q];
            d_h1[rb + t + q * 256] = fmaxf(fmaf(tmp, sc[q], tr[q]), 0.f);
        }
    }
}

// ---------------- fine = h2 @ cw3 + cb3 + pts ----------------
__global__ void fine_kernel(const float* __restrict__ cw3, const float* __restrict__ cb3) {
    int row = blockIdx.x;         // 131072
    int t = threadIdx.x;          // 128
    const float* h = d_h2 + (size_t)row * 1024;
    float a0 = 0.f, a1 = 0.f, a2 = 0.f;
    for (int j = t; j < 1024; j += 128) {
        float x = h[j];
        a0 = fmaf(x, cw3[j * 3 + 0], a0);
        a1 = fmaf(x, cw3[j * 3 + 1], a1);
        a2 = fmaf(x, cw3[j * 3 + 2], a2);
    }
#pragma unroll
    for (int off = 16; off; off >>= 1) {
        a0 += __shfl_down_sync(0xffffffffu, a0, off);
        a1 += __shfl_down_sync(0xffffffffu, a1, off);
        a2 += __shfl_down_sync(0xffffffffu, a2, off);
    }
    __shared__ float s[4][3];
    if ((t & 31) == 0) { int w = t >> 5; s[w][0] = a0; s[w][1] = a1; s[w][2] = a2; }
    __syncthreads();
    if (t == 0) {
        int p = row >> 6, k = row & 63;
        const float* cp = d_coarse + p * 48 + (k >> 2) * 3;
        d_fine[row * 3 + 0] = s[0][0] + s[1][0] + s[2][0] + s[3][0] + cb3[0] + cp[0];
        d_fine[row * 3 + 1] = s[0][1] + s[1][1] + s[2][1] + s[3][1] + cb3[1] + cp[1];
        d_fine[row * 3 + 2] = s[0][2] + s[1][2] + s[2][2] + s[3][2] + cb3[2] + cp[2];
    }
}

// ---------------- Chamfer per patch ----------------
__global__ void chamfer_kernel() {
    int pt = blockIdx.x;          // 2048
    int t = threadIdx.x;          // 64
    __shared__ float F[64][3], G[64][3];
    const float* fr = d_fine + (size_t)pt * 64 * 3;
    const float* gr = d_gxyz + (size_t)pt * 64 * 3;
    for (int i = t; i < 192; i += 64) {
        ((float*)F)[i] = fr[i];
        ((float*)G)[i] = gr[i];
    }
    __syncthreads();
    float fx = F[t][0], fy = F[t][1], fz = F[t][2];
    float gx = G[t][0], gy = G[t][1], gz = G[t][2];
    float rmin = 1e30f, cmin = 1e30f;
#pragma unroll 4
    for (int s = 0; s < 64; s++) {
        float dx = fx - G[s][0], dy = fy - G[s][1], dz = fz - G[s][2];
        rmin = fminf(rmin, dx * dx + dy * dy + dz * dz);
        float ex = F[s][0] - gx, ey = F[s][1] - gy, ez = F[s][2] - gz;
        cmin = fminf(cmin, ex * ex + ey * ey + ez * ez);
    }
    float v = rmin + cmin;
#pragma unroll
    for (int off = 16; off; off >>= 1) v += __shfl_down_sync(0xffffffffu, v, off);
    __shared__ float ws[2];
    if ((t & 31) == 0) ws[t >> 5] = v;
    __syncthreads();
    if (t == 0) d_partial[pt] = ws[0] + ws[1];
}

// ---------------- deterministic final reduction ----------------
__global__ void final_kernel(float* __restrict__ out) {
    __shared__ float s[256];
    int t = threadIdx.x;
    float a = 0.f;
    for (int i = t; i < BP; i += 256) a += d_partial[i];
    s[t] = a;
    __syncthreads();
    for (int o = 128; o; o >>= 1) {
        if (t < o) s[t] += s[t + o];
        __syncthreads();
    }
    if (t == 0) out[0] = s[0] * (1.0f / 131072.0f);
}

// ---------------- launch ----------------
extern "C" void kernel_launch(void* const* d_in, const int* in_sizes, int n_in,
                              void* d_out, int out_size) {
    const float* xyz = (const float*)d_in[0];
    const float* feat = (const float*)d_in[1];
    const float* w1 = (const float*)d_in[2];  const float* b1 = (const float*)d_in[3];
    const float* w2 = (const float*)d_in[4];  const float* b2 = (const float*)d_in[5];
    const float* w3 = (const float*)d_in[6];  const float* b3 = (const float*)d_in[7];
    const float* cw1 = (const float*)d_in[8]; const float* cb1 = (const float*)d_in[9];
    const float* g1 = (const float*)d_in[10]; const float* be1 = (const float*)d_in[11];
    const float* m1 = (const float*)d_in[12]; const float* v1 = (const float*)d_in[13];
    const float* cw2 = (const float*)d_in[14]; const float* cb2 = (const float*)d_in[15];
    const float* g2 = (const float*)d_in[16]; const float* be2 = (const float*)d_in[17];
    const float* m2 = (const float*)d_in[18]; const float* v2 = (const float*)d_in[19];
    const float* cw3 = (const float*)d_in[20]; const float* cb3 = (const float*)d_in[21];

    float *p_pf, *p_ha, *p_hb, *p_base1, *p_h1, *p_h2;
    cudaGetSymbolAddress((void**)&p_pf, d_pf);
    cudaGetSymbolAddress((void**)&p_ha, d_ha);
    cudaGetSymbolAddress((void**)&p_hb, d_hb);
    cudaGetSymbolAddress((void**)&p_base1, d_base1);
    cudaGetSymbolAddress((void**)&p_h1, d_h1);
    cudaGetSymbolAddress((void**)&p_h2, d_h2);

    fps_kernel<<<Bb, 256>>>(xyz);
    topk_kernel<<<BP, 256>>>(xyz);
    pfeat_kernel<<<BP, 128>>>(feat);

    // FoldingNet MLP on patch features
    sgemm_kernel<<<dim3(8, 16), 256>>>(p_pf, w1, b1, 0, 0, 0, 0, p_ha, BP, DFF, Dd, 1);
    sgemm_kernel<<<dim3(8, 16), 256>>>(p_ha, w2, b2, 0, 0, 0, 0, p_hb, BP, DFF, DFF, 1);
    mlp3_kernel<<<BP, 128>>>(w3, b3);

    // conv1 patch-level part, then per-point broadcast + BN + relu
    sgemm_kernel<<<dim3(8, 16), 256>>>(p_pf, cw1, cb1, 0, 0, 0, 0, p_base1, BP, DFF, Dd, 0);
    conv1_kernel<<<BP, 256>>>(cw1, g1, be1, m1, v1);

    // the big GEMM: h2 = relu(bn(h1 @ cw2 + cb2))
    sgemm_kernel<<<dim3(8, 1024), 256>>>(p_h1, cw2, cb2, g2, be2, m2, v2, p_h2,
                                         RT, DFF, DFF, 2);

    fine_kernel<<<RT, 128>>>(cw3, cb3);
    chamfer_kernel<<<BP, 64>>>();
    final_kernel<<<1, 256>>>((float*)d_out);
}

// round 5
// speedup vs baseline: 1.4837x; 1.4837x over previous
#include <cuda_runtime.h>
#include <mma.h>
#include <math.h>
#include <stdint.h>
#include <stddef.h>

using namespace nvcuda;

#define Bb   8
#define Nn   4096
#define Dd   128
#define Pp   256
#define Kk   64
#define DFF  1024
#define BP   2048          // B*P patches
#define RT   131072        // BP*Kk point rows
#define EPSB 1e-5f

// ---------------- scratch (static device memory; no allocations) ----------------
__device__ int   d_fidx[BP];
__device__ int   d_gidx[RT];
__device__ float d_gxyz[RT * 3];
__device__ float d_pf[BP * Dd];
__device__ float d_ha[BP * DFF];
__device__ float d_hb[BP * DFF];
__device__ float d_coarse[BP * 48];
__device__ float d_base1[BP * DFF];
__device__ float d_h1[(size_t)RT * DFF];        // 512 MB
__device__ float d_finepart[(size_t)8 * RT * 3];// 12.6 MB
__device__ float d_fine[RT * 3];
__device__ float d_partial[BP];

// ---------------- helpers ----------------
__device__ __forceinline__ unsigned int sptr(const void* p) {
    unsigned int a;
    asm("{ .reg .u64 t; cvta.to.shared.u64 t, %1; cvt.u32.u64 %0, t; }"
        : "=r"(a) : "l"(p));
    return a;
}
__device__ __forceinline__ void cpa16(unsigned int dst, const float* src) {
    asm volatile("cp.async.cg.shared.global [%0], [%1], 16;" :: "r"(dst), "l"(src));
}
__device__ __forceinline__ void cpcommit() {
    asm volatile("cp.async.commit_group;");
}

// ---------------- FPS: one block per batch, sequential 255 argmax steps ----------------
__global__ void fps_kernel(const float* __restrict__ xyz) {
    int b = blockIdx.x;
    const float* X = xyz + (size_t)b * Nn * 3;
    int t = threadIdx.x;  // 256 threads, 16 points each (strided)

    float px[16], py[16], pz[16], md[16];
#pragma unroll
    for (int i = 0; i < 16; i++) {
        int n = i * 256 + t;
        px[i] = X[n * 3 + 0]; py[i] = X[n * 3 + 1]; pz[i] = X[n * 3 + 2];
        md[i] = 1e10f;
    }
    __shared__ float scx, scy, scz;
    __shared__ float wv[8];
    __shared__ int   wi[8];
    if (t == 0) { d_fidx[b * Pp] = 0; scx = X[0]; scy = X[1]; scz = X[2]; }
    __syncthreads();

    for (int step = 1; step < Pp; step++) {
        float cx = scx, cy = scy, cz = scz;
        float bv = -1e30f; int bn = 0;
#pragma unroll
        for (int i = 0; i < 16; i++) {
            float dx = __fadd_rn(px[i], -cx);
            float dy = __fadd_rn(py[i], -cy);
            float dz = __fadd_rn(pz[i], -cz);
            float d  = __fadd_rn(__fadd_rn(__fmul_rn(dx, dx), __fmul_rn(dy, dy)),
                                 __fmul_rn(dz, dz));
            float m = fminf(md[i], d);
            md[i] = m;
            if (m > bv) { bv = m; bn = i * 256 + t; }
        }
#pragma unroll
        for (int off = 16; off; off >>= 1) {
            float ov = __shfl_down_sync(0xffffffffu, bv, off);
            int   on = __shfl_down_sync(0xffffffffu, bn, off);
            if (ov > bv || (ov == bv && on < bn)) { bv = ov; bn = on; }
        }
        if ((t & 31) == 0) { wv[t >> 5] = bv; wi[t >> 5] = bn; }
        __syncthreads();
        if (t == 0) {
            float fv = wv[0]; int fn = wi[0];
#pragma unroll
            for (int w = 1; w < 8; w++)
                if (wv[w] > fv || (wv[w] == fv && wi[w] < fn)) { fv = wv[w]; fn = wi[w]; }
            d_fidx[b * Pp + step] = fn;
            scx = X[fn * 3 + 0]; scy = X[fn * 3 + 1]; scz = X[fn * 3 + 2];
        }
        __syncthreads();
    }
}

// ---------------- top-K (64 nearest of 4096) per patch + grouped_xyz_norm ----------------
__global__ void topk_kernel(const float* __restrict__ xyz) {
    int pp = blockIdx.x;          // 0..2047
    int b  = pp >> 8;
    const float* X = xyz + (size_t)b * Nn * 3;
    int t = threadIdx.x;          // 256

    __shared__ float sd[16 * 256];
    __shared__ float wv[8];
    __shared__ int   wi[8];
    __shared__ int   sel;

    int cI = d_fidx[pp];
    float cx = X[cI * 3 + 0], cy = X[cI * 3 + 1], cz = X[cI * 3 + 2];

    float mv = 1e30f; int mn = 0x7fffffff;
#pragma unroll
    for (int i = 0; i < 16; i++) {
        int n = i * 256 + t;
        float dx = X[n * 3 + 0] - cx, dy = X[n * 3 + 1] - cy, dz = X[n * 3 + 2] - cz;
        float d = dx * dx + dy * dy + dz * dz;
        sd[i * 256 + t] = d;
        if (d < mv) { mv = d; mn = n; }
    }

    for (int k = 0; k < Kk; k++) {
        float v = mv; int n = mn;
#pragma unroll
        for (int off = 16; off; off >>= 1) {
            float ov = __shfl_down_sync(0xffffffffu, v, off);
            int   on = __shfl_down_sync(0xffffffffu, n, off);
            if (ov < v || (ov == v && on < n)) { v = ov; n = on; }
        }
        if ((t & 31) == 0) { wv[t >> 5] = v; wi[t >> 5] = n; }
        __syncthreads();
        if (t == 0) {
            float fv = wv[0]; int fn = wi[0];
#pragma unroll
            for (int w = 1; w < 8; w++)
                if (wv[w] < fv || (wv[w] == fv && wi[w] < fn)) { fv = wv[w]; fn = wi[w]; }
            sel = fn;
            d_gidx[pp * Kk + k] = fn;
            d_gxyz[(pp * Kk + k) * 3 + 0] = X[fn * 3 + 0] - cx;
            d_gxyz[(pp * Kk + k) * 3 + 1] = X[fn * 3 + 1] - cy;
            d_gxyz[(pp * Kk + k) * 3 + 2] = X[fn * 3 + 2] - cz;
        }
        __syncthreads();
        int s = sel;
        if ((s & 255) == t) {
            sd[(s >> 8) * 256 + t] = 1e30f;
            mv = 1e30f; mn = 0x7fffffff;
#pragma unroll
            for (int i = 0; i < 16; i++) {
                float d = sd[i * 256 + t];
                if (d < mv) { mv = d; mn = i * 256 + t; }
            }
        }
    }
}

// ---------------- patch feature: max over K neighbors ----------------
__global__ void pfeat_kernel(const float* __restrict__ feat) {
    int pp = blockIdx.x;          // 2048
    int b  = pp >> 8;
    int dch = threadIdx.x;        // 128
    const float* F = feat + (size_t)b * Nn * Dd;
    float mx = -1e30f;
#pragma unroll 4
    for (int k = 0; k < Kk; k++) {
        int n = d_gidx[pp * Kk + k];
        mx = fmaxf(mx, F[(size_t)n * Dd + dch]);
    }
    d_pf[pp * Dd + dch] = mx;
}

// ---------------- generic fp32 SGEMM 128x128x8 (small GEMMs only) ----------------
// mode 0: +bias ; mode 1: +bias, relu
__global__ __launch_bounds__(256) void sgemm_kernel(
    const float* __restrict__ A, const float* __restrict__ B, const float* __restrict__ bias,
    float* __restrict__ C, int M, int N, int K, int mode)
{
    __shared__ float As[8][128];
    __shared__ float Bs[8][128];
    int tid = threadIdx.x;
    int bx = blockIdx.x, by = blockIdx.y;
    int tx = tid & 15, ty = tid >> 4;
    int row0 = by * 128, col0 = bx * 128;
    int ar = tid >> 1, ac = (tid & 1) * 4;
    int br = tid >> 5, bc = (tid & 31) * 4;
    const float* Ap = A + (size_t)(row0 + ar) * K + ac;
    const float* Bp = B + (size_t)br * N + col0 + bc;

    float acc[8][8];
#pragma unroll
    for (int i = 0; i < 8; i++)
#pragma unroll
        for (int j = 0; j < 8; j++) acc[i][j] = 0.f;

    for (int kt = 0; kt < K; kt += 8) {
        float4 a4 = *(const float4*)(Ap + kt);
        float4 b4 = *(const float4*)(Bp + (size_t)kt * N);
        __syncthreads();
        As[ac + 0][ar] = a4.x; As[ac + 1][ar] = a4.y;
        As[ac + 2][ar] = a4.z; As[ac + 3][ar] = a4.w;
        *(float4*)(&Bs[br][bc]) = b4;
        __syncthreads();
#pragma unroll
        for (int k = 0; k < 8; k++) {
            float a[8], bfr[8];
#pragma unroll
            for (int i = 0; i < 8; i++) a[i] = As[k][ty * 8 + i];
#pragma unroll
            for (int j = 0; j < 8; j++) bfr[j] = Bs[k][tx * 8 + j];
#pragma unroll
            for (int i = 0; i < 8; i++)
#pragma unroll
                for (int j = 0; j < 8; j++) acc[i][j] = fmaf(a[i], bfr[j], acc[i][j]);
        }
    }

#pragma unroll
    for (int j = 0; j < 8; j++) {
        int c = col0 + tx * 8 + j;
        float tb = bias[c];
#pragma unroll
        for (int i = 0; i < 8; i++) {
            int r = row0 + ty * 8 + i;
            float x = acc[i][j] + tb;
            if (mode >= 1) x = fmaxf(x, 0.f);
            C[(size_t)r * N + c] = x;
        }
    }
}

// ---------------- MLP layer 3 (N=48): coarse = hb @ w3 + b3 ----------------
__global__ void mlp3_kernel(const float* __restrict__ w3, const float* __restrict__ b3) {
    int row = blockIdx.x;         // 2048
    __shared__ float a[1024];
    int t = threadIdx.x;          // 128
    for (int i = t; i < 1024; i += 128) a[i] = d_hb[(size_t)row * 1024 + i];
    __syncthreads();
    if (t < 48) {
        float s0 = 0.f, s1 = 0.f, s2 = 0.f, s3 = 0.f;
#pragma unroll 4
        for (int k = 0; k < 1024; k += 4) {
            s0 = fmaf(a[k + 0], w3[(k + 0) * 48 + t], s0);
            s1 = fmaf(a[k + 1], w3[(k + 1) * 48 + t], s1);
            s2 = fmaf(a[k + 2], w3[(k + 2) * 48 + t], s2);
            s3 = fmaf(a[k + 3], w3[(k + 3) * 48 + t], s3);
        }
        d_coarse[row * 48 + t] = ((s0 + s1) + (s2 + s3)) + b3[t];
    }
}

// ---------------- conv layer 1: h1 = relu(bn(base1 + seed/pts rank-1 terms)) ----------------
__global__ void conv1_kernel(const float* __restrict__ cw1, const float* __restrict__ g1,
                             const float* __restrict__ be1, const float* __restrict__ m1,
                             const float* __restrict__ v1) {
    int p = blockIdx.x;           // 2048 patches
    int t = threadIdx.x;          // 256
    float bs[4], c0[4], c1[4], c2[4], c3[4], c4[4], sc[4], tr[4];
#pragma unroll
    for (int q = 0; q < 4; q++) {
        int j = t + q * 256;
        bs[q] = d_base1[p * 1024 + j];
        c0[q] = cw1[128 * 1024 + j];
        c1[q] = cw1[129 * 1024 + j];
        c2[q] = cw1[130 * 1024 + j];
        c3[q] = cw1[131 * 1024 + j];
        c4[q] = cw1[132 * 1024 + j];
        float s = g1[j] * rsqrtf(v1[j] + EPSB);
        sc[q] = s;
        tr[q] = be1[j] - m1[j] * s;
    }
    for (int k = 0; k < 64; k++) {
        float sx = (k & 1) ? 0.05f : -0.05f;
        float sy = (k & 2) ? 0.05f : -0.05f;
        const float* cp = d_coarse + p * 48 + (k >> 2) * 3;
        float px = cp[0], py = cp[1], pz = cp[2];
        size_t rb = ((size_t)(p * 64 + k)) * 1024;
#pragma unroll
        for (int q = 0; q < 4; q++) {
            float tmp = bs[q] + sx * c0[q] + sy * c1[q] + px * c2[q] + py * c3[q] + pz * c4[q];
            d_h1[rb + t + q * 256] = fmaxf(fmaf(tmp, sc[q], tr[q]), 0.f);
        }
    }
}

// ================= conv2 tf32 tensor-core GEMM, fused BN+relu+conv3 =================
// C-tile 128x128, K-chunk 32, cp.async double-buffered, 8 warps, warp tile 64x32.
// Epilogue contracts the h2 tile with the cw3 chunk -> 128x3 partial per N-chunk.
#define A_LD 36
#define B_LD 132
#define A_BUF (128 * A_LD)   // 4608 floats
#define B_BUF (32 * B_LD)    // 4224 floats
#define DYN_FLOATS (2 * A_BUF + 2 * B_BUF)   // 17664 floats = 70656 B

__global__ __launch_bounds__(256) void conv2_wmma_kernel(
    const float* __restrict__ A,    // d_h1 [RT][1024]
    const float* __restrict__ Bw,   // cw2 [1024][1024]
    const float* __restrict__ cb2, const float* __restrict__ g2,
    const float* __restrict__ be2, const float* __restrict__ m2,
    const float* __restrict__ v2,  const float* __restrict__ cw3,
    float* __restrict__ finepart)
{
    extern __shared__ float dyn[];
    float* As = dyn;                 // [2][128][A_LD]
    float* Bs = dyn + 2 * A_BUF;     // [2][32][B_LD]
    float* Cs = dyn;                 // reuse: [128][B_LD]

    __shared__ float s_scale[128], s_tb[128], s_cw3[3][128];

    int tid = threadIdx.x;
    int wid = tid >> 5;
    int wm = wid >> 2;               // 0..1
    int wn = wid & 3;                // 0..3
    int bx = blockIdx.x;             // N chunk 0..7
    int by = blockIdx.y;             // row band 0..1023
    int col0 = bx * 128;
    int row0 = by * 128;

    if (tid < 128) {
        int c = col0 + tid;
        float sc = g2[c] * rsqrtf(v2[c] + EPSB);
        s_scale[tid] = sc;
        s_tb[tid] = (cb2[c] - m2[c]) * sc + be2[c];
        s_cw3[0][tid] = cw3[c * 3 + 0];
        s_cw3[1][tid] = cw3[c * 3 + 1];
        s_cw3[2][tid] = cw3[c * 3 + 2];
    }

    // staging thread mapping
    int ar = tid >> 1;               // row 0..127
    int ac = (tid & 1) * 16;         // 0 or 16 floats
    const float* Ag = A + (size_t)(row0 + ar) * 1024 + ac;
    int bk = tid >> 5;               // 0..7 (base k, +8q)
    int bc = (tid & 31) * 4;         // col floats

    unsigned int smA = sptr(As);
    unsigned int smB = sptr(Bs);

    wmma::fragment<wmma::accumulator, 16, 16, 8, float> acc[4][2];
#pragma unroll
    for (int mi = 0; mi < 4; mi++)
#pragma unroll
        for (int ni = 0; ni < 2; ni++) wmma::fill_fragment(acc[mi][ni], 0.f);

    // issue k-tile kt into buffer buf
    auto issue = [&](int kt, int buf) {
        unsigned int adst = smA + (unsigned int)((buf * A_BUF + ar * A_LD + ac) * 4);
        const float* asrc = Ag + kt * 32;
        cpa16(adst + 0u,  asrc + 0);
        cpa16(adst + 16u, asrc + 4);
        cpa16(adst + 32u, asrc + 8);
        cpa16(adst + 48u, asrc + 12);
        unsigned int bdst = smB + (unsigned int)((buf * B_BUF + bk * B_LD + bc) * 4);
#pragma unroll
        for (int q = 0; q < 4; q++) {
            const float* bsrc = Bw + ((size_t)(kt * 32 + bk + 8 * q)) * 1024 + col0 + bc;
            cpa16(bdst + (unsigned int)(q * 8 * B_LD * 4), bsrc);
        }
    };

    issue(0, 0);
    cpcommit();

    for (int kt = 0; kt < 32; kt++) {
        int buf = kt & 1;
        if (kt + 1 < 32) {
            issue(kt + 1, buf ^ 1);
            cpcommit();
            asm volatile("cp.async.wait_group 1;");
        } else {
            asm volatile("cp.async.wait_group 0;");
        }
        __syncthreads();

        const float* Ab = As + buf * A_BUF;
        const float* Bb_ = Bs + buf * B_BUF;
#pragma unroll
        for (int k8 = 0; k8 < 4; k8++) {
            wmma::fragment<wmma::matrix_a, 16, 16, 8, wmma::precision::tf32, wmma::row_major> af[4];
            wmma::fragment<wmma::matrix_b, 16, 16, 8, wmma::precision::tf32, wmma::row_major> bf[2];
#pragma unroll
            for (int mi = 0; mi < 4; mi++) {
                wmma::load_matrix_sync(af[mi], Ab + (wm * 64 + mi * 16) * A_LD + k8 * 8, A_LD);
#pragma unroll
                for (int e = 0; e < af[mi].num_elements; e++)
                    af[mi].x[e] = wmma::__float_to_tf32(af[mi].x[e]);
            }
#pragma unroll
            for (int ni = 0; ni < 2; ni++) {
                wmma::load_matrix_sync(bf[ni], Bb_ + (k8 * 8) * B_LD + wn * 32 + ni * 16, B_LD);
#pragma unroll
                for (int e = 0; e < bf[ni].num_elements; e++)
                    bf[ni].x[e] = wmma::__float_to_tf32(bf[ni].x[e]);
            }
#pragma unroll
            for (int mi = 0; mi < 4; mi++)
#pragma unroll
                for (int ni = 0; ni < 2; ni++)
                    wmma::mma_sync(acc[mi][ni], af[mi], bf[ni], acc[mi][ni]);
        }
        __syncthreads();
    }

    // epilogue: store tile, apply BN+relu, contract with cw3 chunk
#pragma unroll
    for (int mi = 0; mi < 4; mi++)
#pragma unroll
        for (int ni = 0; ni < 2; ni++)
            wmma::store_matrix_sync(Cs + (wm * 64 + mi * 16) * B_LD + wn * 32 + ni * 16,
                                    acc[mi][ni], B_LD, wmma::mem_row_major);
    __syncthreads();

    if (tid < 128) {
        int r = tid;
        const float* cr = Cs + r * B_LD;
        float s0 = 0.f, s1 = 0.f, s2 = 0.f;
#pragma unroll 4
        for (int c = 0; c < 128; c++) {
            float x = fmaxf(fmaf(cr[c], s_scale[c], s_tb[c]), 0.f);
            s0 = fmaf(x, s_cw3[0][c], s0);
            s1 = fmaf(x, s_cw3[1][c], s1);
            s2 = fmaf(x, s_cw3[2][c], s2);
        }
        size_t rg = (size_t)row0 + r;
        finepart[((size_t)bx * RT + rg) * 3 + 0] = s0;
        finepart[((size_t)bx * RT + rg) * 3 + 1] = s1;
        finepart[((size_t)bx * RT + rg) * 3 + 2] = s2;
    }
}

// ---------------- reduce fine partials (fixed order -> deterministic) ----------------
__global__ void finered_kernel(const float* __restrict__ cb3) {
    int row = blockIdx.x * 256 + threadIdx.x;     // RT total
    float s0 = cb3[0], s1 = cb3[1], s2 = cb3[2];
#pragma unroll
    for (int bx = 0; bx < 8; bx++) {
        const float* fp = d_finepart + ((size_t)bx * RT + row) * 3;
        s0 += fp[0]; s1 += fp[1]; s2 += fp[2];
    }
    int p = row >> 6, k = row & 63;
    const float* cp = d_coarse + p * 48 + (k >> 2) * 3;
    d_fine[row * 3 + 0] = s0 + cp[0];
    d_fine[row * 3 + 1] = s1 + cp[1];
    d_fine[row * 3 + 2] = s2 + cp[2];
}

// ---------------- Chamfer per patch ----------------
__global__ void chamfer_kernel() {
    int pt = blockIdx.x;          // 2048
    int t = threadIdx.x;          // 64
    __shared__ float F[64][3], G[64][3];
    const float* fr = d_fine + (size_t)pt * 64 * 3;
    const float* gr = d_gxyz + (size_t)pt * 64 * 3;
    for (int i = t; i < 192; i += 64) {
        ((float*)F)[i] = fr[i];
        ((float*)G)[i] = gr[i];
    }
    __syncthreads();
    float fx = F[t][0], fy = F[t][1], fz = F[t][2];
    float gx = G[t][0], gy = G[t][1], gz = G[t][2];
    float rmin = 1e30f, cmin = 1e30f;
#pragma unroll 4
    for (int s = 0; s < 64; s++) {
        float dx = fx - G[s][0], dy = fy - G[s][1], dz = fz - G[s][2];
        rmin = fminf(rmin, dx * dx + dy * dy + dz * dz);
        float ex = F[s][0] - gx, ey = F[s][1] - gy, ez = F[s][2] - gz;
        cmin = fminf(cmin, ex * ex + ey * ey + ez * ez);
    }
    float v = rmin + cmin;
#pragma unroll
    for (int off = 16; off; off >>= 1) v += __shfl_down_sync(0xffffffffu, v, off);
    __shared__ float ws[2];
    if ((t & 31) == 0) ws[t >> 5] = v;
    __syncthreads();
    if (t == 0) d_partial[pt] = ws[0] + ws[1];
}

// ---------------- deterministic final reduction ----------------
__global__ void final_kernel(float* __restrict__ out) {
    __shared__ float s[256];
    int t = threadIdx.x;
    float a = 0.f;
    for (int i = t; i < BP; i += 256) a += d_partial[i];
    s[t] = a;
    __syncthreads();
    for (int o = 128; o; o >>= 1) {
        if (t < o) s[t] += s[t + o];
        __syncthreads();
    }
    if (t == 0) out[0] = s[0] * (1.0f / 131072.0f);
}

// ---------------- launch ----------------
extern "C" void kernel_launch(void* const* d_in, const int* in_sizes, int n_in,
                              void* d_out, int out_size) {
    const float* xyz = (const float*)d_in[0];
    const float* feat = (const float*)d_in[1];
    const float* w1 = (const float*)d_in[2];  const float* b1 = (const float*)d_in[3];
    const float* w2 = (const float*)d_in[4];  const float* b2 = (const float*)d_in[5];
    const float* w3 = (const float*)d_in[6];  const float* b3 = (const float*)d_in[7];
    const float* cw1 = (const float*)d_in[8]; const float* cb1 = (const float*)d_in[9];
    const float* g1 = (const float*)d_in[10]; const float* be1 = (const float*)d_in[11];
    const float* m1 = (const float*)d_in[12]; const float* v1 = (const float*)d_in[13];
    const float* cw2 = (const float*)d_in[14]; const float* cb2 = (const float*)d_in[15];
    const float* g2 = (const float*)d_in[16]; const float* be2 = (const float*)d_in[17];
    const float* m2 = (const float*)d_in[18]; const float* v2 = (const float*)d_in[19];
    const float* cw3 = (const float*)d_in[20]; const float* cb3 = (const float*)d_in[21];

    float *p_pf, *p_ha, *p_hb, *p_base1, *p_h1, *p_fp;
    cudaGetSymbolAddress((void**)&p_pf, d_pf);
    cudaGetSymbolAddress((void**)&p_ha, d_ha);
    cudaGetSymbolAddress((void**)&p_hb, d_hb);
    cudaGetSymbolAddress((void**)&p_base1, d_base1);
    cudaGetSymbolAddress((void**)&p_h1, d_h1);
    cudaGetSymbolAddress((void**)&p_fp, d_finepart);

    cudaFuncSetAttribute(conv2_wmma_kernel,
                         cudaFuncAttributeMaxDynamicSharedMemorySize,
                         DYN_FLOATS * 4);

    fps_kernel<<<Bb, 256>>>(xyz);
    topk_kernel<<<BP, 256>>>(xyz);
    pfeat_kernel<<<BP, 128>>>(feat);

    // FoldingNet MLP on patch features
    sgemm_kernel<<<dim3(8, 16), 256>>>(p_pf, w1, b1, p_ha, BP, DFF, Dd, 1);
    sgemm_kernel<<<dim3(8, 16), 256>>>(p_ha, w2, b2, p_hb, BP, DFF, DFF, 1);
    mlp3_kernel<<<BP, 128>>>(w3, b3);

    // conv1 patch-level part, then per-point broadcast + BN + relu
    sgemm_kernel<<<dim3(8, 16), 256>>>(p_pf, cw1, cb1, p_base1, BP, DFF, Dd, 0);
    conv1_kernel<<<BP, 256>>>(cw1, g1, be1, m1, v1);

    // big GEMM on tensor cores (tf32), fused BN+relu+conv3 epilogue
    conv2_wmma_kernel<<<dim3(8, 1024), 256, DYN_FLOATS * 4>>>(
        p_h1, cw2, cb2, g2, be2, m2, v2, cw3, p_fp);

    finered_kernel<<<RT / 256, 256>>>(cb3);
    chamfer_kernel<<<BP, 64>>>();
    final_kernel<<<1, 256>>>((float*)d_out);
}

// round 7
// speedup vs baseline: 3.7265x; 2.5117x over previous
#include <cuda_runtime.h>
#include <cuda_bf16.h>
#include <mma.h>
#include <math.h>
#include <stdint.h>
#include <stddef.h>

using namespace nvcuda;

#define Bb   8
#define Nn   4096
#define Dd   128
#define Pp   256
#define Kk   64
#define DFF  1024
#define BP   2048          // B*P patches
#define RT   131072        // BP*Kk point rows
#define EPSB 1e-5f

// ---------------- scratch (static device memory; no allocations) ----------------
__device__ int   d_fidx[BP];
__device__ int   d_gidx[RT];
__device__ float d_gxyz[RT * 3];
__device__ float d_pf[BP * Dd];
__device__ float d_ha[BP * DFF];
__device__ float d_hb[BP * DFF];
__device__ float d_coarse[BP * 48];
__device__ float d_base1[BP * DFF];
__device__ __nv_bfloat16 d_cw2b[DFF * DFF];      // BN-scaled bf16 cw2 (2 MB)
__device__ float d_finepart[(size_t)8 * RT * 3]; // 12.6 MB
__device__ float d_fine[RT * 3];
__device__ float d_partial[BP];

// ---------------- helpers ----------------
__device__ __forceinline__ unsigned int sptr(const void* p) {
    unsigned int a;
    asm("{ .reg .u64 t; cvta.to.shared.u64 t, %1; cvt.u32.u64 %0, t; }"
        : "=r"(a) : "l"(p));
    return a;
}
__device__ __forceinline__ void cpa16(unsigned int dst, const void* src) {
    asm volatile("cp.async.cg.shared.global [%0], [%1], 16;" :: "r"(dst), "l"(src));
}
__device__ __forceinline__ void cpcommit() {
    asm volatile("cp.async.commit_group;");
}

// ---------------- FPS: one block per batch, sequential 255 argmax steps ----------------
__global__ void fps_kernel(const float* __restrict__ xyz) {
    int b = blockIdx.x;
    const float* X = xyz + (size_t)b * Nn * 3;
    int t = threadIdx.x;  // 256 threads, 16 points each (strided)

    float px[16], py[16], pz[16], md[16];
#pragma unroll
    for (int i = 0; i < 16; i++) {
        int n = i * 256 + t;
        px[i] = X[n * 3 + 0]; py[i] = X[n * 3 + 1]; pz[i] = X[n * 3 + 2];
        md[i] = 1e10f;
    }
    __shared__ float scx, scy, scz;
    __shared__ float wv[8];
    __shared__ int   wi[8];
    if (t == 0) { d_fidx[b * Pp] = 0; scx = X[0]; scy = X[1]; scz = X[2]; }
    __syncthreads();

    for (int step = 1; step < Pp; step++) {
        float cx = scx, cy = scy, cz = scz;
        float bv = -1e30f; int bn = 0;
#pragma unroll
        for (int i = 0; i < 16; i++) {
            float dx = __fadd_rn(px[i], -cx);
            float dy = __fadd_rn(py[i], -cy);
            float dz = __fadd_rn(pz[i], -cz);
            float d  = __fadd_rn(__fadd_rn(__fmul_rn(dx, dx), __fmul_rn(dy, dy)),
                                 __fmul_rn(dz, dz));
            float m = fminf(md[i], d);
            md[i] = m;
            if (m > bv) { bv = m; bn = i * 256 + t; }
        }
#pragma unroll
        for (int off = 16; off; off >>= 1) {
            float ov = __shfl_down_sync(0xffffffffu, bv, off);
            int   on = __shfl_down_sync(0xffffffffu, bn, off);
            if (ov > bv || (ov == bv && on < bn)) { bv = ov; bn = on; }
        }
        if ((t & 31) == 0) { wv[t >> 5] = bv; wi[t >> 5] = bn; }
        __syncthreads();
        if (t == 0) {
            float fv = wv[0]; int fn = wi[0];
#pragma unroll
            for (int w = 1; w < 8; w++)
                if (wv[w] > fv || (wv[w] == fv && wi[w] < fn)) { fv = wv[w]; fn = wi[w]; }
            d_fidx[b * Pp + step] = fn;
            scx = X[fn * 3 + 0]; scy = X[fn * 3 + 1]; scz = X[fn * 3 + 2];
        }
        __syncthreads();
    }
}

// ---------------- top-K (64 nearest of 4096) per patch + grouped_xyz_norm ----------------
__global__ void topk_kernel(const float* __restrict__ xyz) {
    int pp = blockIdx.x;          // 0..2047
    int b  = pp >> 8;
    const float* X = xyz + (size_t)b * Nn * 3;
    int t = threadIdx.x;          // 256

    __shared__ float sd[16 * 256];
    __shared__ float wv[8];
    __shared__ int   wi[8];
    __shared__ int   sel;

    int cI = d_fidx[pp];
    float cx = X[cI * 3 + 0], cy = X[cI * 3 + 1], cz = X[cI * 3 + 2];

    float mv = 1e30f; int mn = 0x7fffffff;
#pragma unroll
    for (int i = 0; i < 16; i++) {
        int n = i * 256 + t;
        float dx = X[n * 3 + 0] - cx, dy = X[n * 3 + 1] - cy, dz = X[n * 3 + 2] - cz;
        float d = dx * dx + dy * dy + dz * dz;
        sd[i * 256 + t] = d;
        if (d < mv) { mv = d; mn = n; }
    }

    for (int k = 0; k < Kk; k++) {
        float v = mv; int n = mn;
#pragma unroll
        for (int off = 16; off; off >>= 1) {
            float ov = __shfl_down_sync(0xffffffffu, v, off);
            int   on = __shfl_down_sync(0xffffffffu, n, off);
            if (ov < v || (ov == v && on < n)) { v = ov; n = on; }
        }
        if ((t & 31) == 0) { wv[t >> 5] = v; wi[t >> 5] = n; }
        __syncthreads();
        if (t == 0) {
            float fv = wv[0]; int fn = wi[0];
#pragma unroll
            for (int w = 1; w < 8; w++)
                if (wv[w] < fv || (wv[w] == fv && wi[w] < fn)) { fv = wv[w]; fn = wi[w]; }
            sel = fn;
            d_gidx[pp * Kk + k] = fn;
            d_gxyz[(pp * Kk + k) * 3 + 0] = X[fn * 3 + 0] - cx;
            d_gxyz[(pp * Kk + k) * 3 + 1] = X[fn * 3 + 1] - cy;
            d_gxyz[(pp * Kk + k) * 3 + 2] = X[fn * 3 + 2] - cz;
        }
        __syncthreads();
        int s = sel;
        if ((s & 255) == t) {
            sd[(s >> 8) * 256 + t] = 1e30f;
            mv = 1e30f; mn = 0x7fffffff;
#pragma unroll
            for (int i = 0; i < 16; i++) {
                float d = sd[i * 256 + t];
                if (d < mv) { mv = d; mn = i * 256 + t; }
            }
        }
    }
}

// ---------------- patch feature: max over K neighbors ----------------
__global__ void pfeat_kernel(const float* __restrict__ feat) {
    int pp = blockIdx.x;          // 2048
    int b  = pp >> 8;
    int dch = threadIdx.x;        // 128
    const float* F = feat + (size_t)b * Nn * Dd;
    float mx = -1e30f;
#pragma unroll 4
    for (int k = 0; k < Kk; k++) {
        int n = d_gidx[pp * Kk + k];
        mx = fmaxf(mx, F[(size_t)n * Dd + dch]);
    }
    d_pf[pp * Dd + dch] = mx;
}

// ---------------- generic fp32 SGEMM 128x128x8 (small GEMMs only) ----------------
// mode 0: +bias ; mode 1: +bias, relu
__global__ __launch_bounds__(256) void sgemm_kernel(
    const float* __restrict__ A, const float* __restrict__ B, const float* __restrict__ bias,
    float* __restrict__ C, int M, int N, int K, int mode)
{
    __shared__ float As[8][128];
    __shared__ float Bs[8][128];
    int tid = threadIdx.x;
    int bx = blockIdx.x, by = blockIdx.y;
    int tx = tid & 15, ty = tid >> 4;
    int row0 = by * 128, col0 = bx * 128;
    int ar = tid >> 1, ac = (tid & 1) * 4;
    int br = tid >> 5, bc = (tid & 31) * 4;
    const float* Ap = A + (size_t)(row0 + ar) * K + ac;
    const float* Bp = B + (size_t)br * N + col0 + bc;

    float acc[8][8];
#pragma unroll
    for (int i = 0; i < 8; i++)
#pragma unroll
        for (int j = 0; j < 8; j++) acc[i][j] = 0.f;

    for (int kt = 0; kt < K; kt += 8) {
        float4 a4 = *(const float4*)(Ap + kt);
        float4 b4 = *(const float4*)(Bp + (size_t)kt * N);
        __syncthreads();
        As[ac + 0][ar] = a4.x; As[ac + 1][ar] = a4.y;
        As[ac + 2][ar] = a4.z; As[ac + 3][ar] = a4.w;
        *(float4*)(&Bs[br][bc]) = b4;
        __syncthreads();
#pragma unroll
        for (int k = 0; k < 8; k++) {
            float a[8], bfr[8];
#pragma unroll
            for (int i = 0; i < 8; i++) a[i] = As[k][ty * 8 + i];
#pragma unroll
            for (int j = 0; j < 8; j++) bfr[j] = Bs[k][tx * 8 + j];
#pragma unroll
            for (int i = 0; i < 8; i++)
#pragma unroll
                for (int j = 0; j < 8; j++) acc[i][j] = fmaf(a[i], bfr[j], acc[i][j]);
        }
    }

#pragma unroll
    for (int j = 0; j < 8; j++) {
        int c = col0 + tx * 8 + j;
        float tb = bias[c];
#pragma unroll
        for (int i = 0; i < 8; i++) {
            int r = row0 + ty * 8 + i;
            float x = acc[i][j] + tb;
            if (mode >= 1) x = fmaxf(x, 0.f);
            C[(size_t)r * N + c] = x;
        }
    }
}

// ---------------- MLP layer 3 (N=48): coarse = hb @ w3 + b3 ----------------
__global__ void mlp3_kernel(const float* __restrict__ w3, const float* __restrict__ b3) {
    int row = blockIdx.x;         // 2048
    __shared__ float a[1024];
    int t = threadIdx.x;          // 128
    for (int i = t; i < 1024; i += 128) a[i] = d_hb[(size_t)row * 1024 + i];
    __syncthreads();
    if (t < 48) {
        float s0 = 0.f, s1 = 0.f, s2 = 0.f, s3 = 0.f;
#pragma unroll 4
        for (int k = 0; k < 1024; k += 4) {
            s0 = fmaf(a[k + 0], w3[(k + 0) * 48 + t], s0);
            s1 = fmaf(a[k + 1], w3[(k + 1) * 48 + t], s1);
            s2 = fmaf(a[k + 2], w3[(k + 2) * 48 + t], s2);
            s3 = fmaf(a[k + 3], w3[(k + 3) * 48 + t], s3);
        }
        d_coarse[row * 48 + t] = ((s0 + s1) + (s2 + s3)) + b3[t];
    }
}

// ---------------- prescale cw2 by BN scale, convert to bf16 ----------------
__global__ void prescale_kernel(const float* __restrict__ cw2,
                                const float* __restrict__ g2,
                                const float* __restrict__ v2) {
    int idx = blockIdx.x * 256 + threadIdx.x;   // 1M total
    int c = idx & 1023;
    float sc = g2[c] * rsqrtf(v2[c] + EPSB);
    d_cw2b[idx] = __float2bfloat16(cw2[idx] * sc);
}

// ================= fused conv1+conv2 bf16 tensor-core GEMM + BN+relu+conv3 =================
// C-tile 128x128 (= 2 patches x 64 pts), K-chunk 32; A-tile (h1) computed in-kernel from
// base1 + rank-5 seed/pts terms; B (BN-scaled bf16 cw2) via cp.async double buffer.
// Epilogue contracts the h2 tile with the cw3 chunk -> 128x3 partial per N-chunk.
#define AB_LD 40                  // bf16 elems per A row (32 + 8 pad)
#define BB_LD 136                 // bf16 elems per B row (128 + 8 pad)
#define A_TILE (128 * AB_LD)      // 5120 bf16
#define B_TILE (32 * BB_LD)       // 4352 bf16
#define C_LD   132
#define DYN_BYTES 67584           // max(2*A_TILE*2 + 2*B_TILE*2 = 37888, 128*C_LD*4 = 67584)

__global__ __launch_bounds__(256) void conv2_fused_kernel(
    const float* __restrict__ base1,
    const float* __restrict__ cw1, const float* __restrict__ g1,
    const float* __restrict__ be1, const float* __restrict__ m1,
    const float* __restrict__ v1,
    const float* __restrict__ cb2, const float* __restrict__ g2,
    const float* __restrict__ be2, const float* __restrict__ m2,
    const float* __restrict__ v2,  const float* __restrict__ cw3,
    float* __restrict__ finepart)
{
    extern __shared__ char dynS[];
    __nv_bfloat16* As = (__nv_bfloat16*)dynS;                        // [2][128][AB_LD]
    __nv_bfloat16* Bs = (__nv_bfloat16*)(dynS + 2 * A_TILE * 2);     // [2][32][BB_LD]
    float* Cs = (float*)dynS;                                        // reuse: [128][C_LD]

    __shared__ float s_bias2[128], s_cw3[3][128];

    int tid = threadIdx.x;
    int wid = tid >> 5;
    int wm = wid >> 2;               // 0..1
    int wn = wid & 3;                // 0..3
    int bx = blockIdx.x;             // N chunk 0..7
    int by = blockIdx.y;             // row band 0..1023
    int col0 = bx * 128;
    int row0 = by * 128;

    if (tid < 128) {
        int c = col0 + tid;
        float sc = g2[c] * rsqrtf(v2[c] + EPSB);
        s_bias2[tid] = (cb2[c] - m2[c]) * sc + be2[c];
        s_cw3[0][tid] = cw3[c * 3 + 0];
        s_cw3[1][tid] = cw3[c * 3 + 1];
        s_cw3[2][tid] = cw3[c * 3 + 2];
    }

    // A-compute role: thread -> channel j, row group g (16 rows, one patch, 4 coarse pts)
    int j = tid & 31;
    int g = wid;                         // 0..7
    int pr = by * 2 + (g >> 2);          // patch
    float px[4], py[4], pz[4];
    {
        const float* cpb = d_coarse + pr * 48 + (g & 3) * 12;
#pragma unroll
        for (int m = 0; m < 4; m++) {
            px[m] = cpb[m * 3 + 0]; py[m] = cpb[m * 3 + 1]; pz[m] = cpb[m * 3 + 2];
        }
    }
    const size_t prbase = (size_t)pr * 1024;

    wmma::fragment<wmma::accumulator, 16, 16, 16, float> acc[4][2];
#pragma unroll
    for (int mi = 0; mi < 4; mi++)
#pragma unroll
        for (int ni = 0; ni < 2; ni++) wmma::fill_fragment(acc[mi][ni], 0.f);

    // compute h1 column j, rows g*16..+16 for channel chunk kt -> As[buf]
    auto computeA = [&](int kt, int buf) {
        int c = kt * 32 + j;
        float base = base1[prbase + c];
        float w0 = cw1[128 * 1024 + c];
        float w1v = cw1[129 * 1024 + c];
        float w2v = cw1[130 * 1024 + c];
        float w3v = cw1[131 * 1024 + c];
        float w4v = cw1[132 * 1024 + c];
        float scl = g1[c] * rsqrtf(v1[c] + EPSB);
        float trn = be1[c] - m1[c] * scl;
        float u0 = scl * w0, u1 = scl * w1v;
        float u2 = scl * w2v, u3 = scl * w3v, u4 = scl * w4v;
        float bb = scl * base + trn;
        float a0 = 0.05f * u0, a1 = 0.05f * u1;
        __nv_bfloat16* Ab = As + buf * A_TILE + (g * 16) * AB_LD + j;
#pragma unroll
        for (int m = 0; m < 4; m++) {
            float tm = bb + px[m] * u2 + py[m] * u3 + pz[m] * u4;
            float e0 = tm - a0 - a1;   // (sx=-, sy=-)
            float e1 = tm + a0 - a1;   // (sx=+, sy=-)
            float e2 = tm - a0 + a1;   // (sx=-, sy=+)
            float e3 = tm + a0 + a1;   // (sx=+, sy=+)
            Ab[(m * 4 + 0) * AB_LD] = __float2bfloat16(fmaxf(e0, 0.f));
            Ab[(m * 4 + 1) * AB_LD] = __float2bfloat16(fmaxf(e1, 0.f));
            Ab[(m * 4 + 2) * AB_LD] = __float2bfloat16(fmaxf(e2, 0.f));
            Ab[(m * 4 + 3) * AB_LD] = __float2bfloat16(fmaxf(e3, 0.f));
        }
    };

    // B staging: 8 KB chunk; each thread copies two 16B segments
    auto issueB = [&](int kt, int buf) {
#pragma unroll
        for (int s = 0; s < 2; s++) {
            int seg = tid + s * 256;
            int rr = seg >> 4;             // 0..31 (k row within chunk)
            int cs = (seg & 15) * 8;       // bf16 col offset
            unsigned int dst = sptr(Bs + buf * B_TILE + rr * BB_LD + cs);
            const __nv_bfloat16* src = d_cw2b + (size_t)(kt * 32 + rr) * 1024 + col0 + cs;
            cpa16(dst, src);
        }
    };

    issueB(0, 0);
    cpcommit();
    computeA(0, 0);

    for (int kt = 0; kt < 32; kt++) {
        int buf = kt & 1;
        asm volatile("cp.async.wait_group 0;");
        __syncthreads();                       // B(kt) + A(kt) visible; prior-buf reads done
        if (kt < 31) { issueB(kt + 1, buf ^ 1); cpcommit(); }

        const __nv_bfloat16* Ab = As + buf * A_TILE;
        const __nv_bfloat16* Bb2 = Bs + buf * B_TILE;
#pragma unroll
        for (int kk = 0; kk < 2; kk++) {
            wmma::fragment<wmma::matrix_a, 16, 16, 16, __nv_bfloat16, wmma::row_major> af[4];
            wmma::fragment<wmma::matrix_b, 16, 16, 16, __nv_bfloat16, wmma::row_major> bf2[2];
#pragma unroll
            for (int mi = 0; mi < 4; mi++)
                wmma::load_matrix_sync(af[mi], Ab + (wm * 64 + mi * 16) * AB_LD + kk * 16, AB_LD);
#pragma unroll
            for (int ni = 0; ni < 2; ni++)
                wmma::load_matrix_sync(bf2[ni], Bb2 + (kk * 16) * BB_LD + wn * 32 + ni * 16, BB_LD);
#pragma unroll
            for (int mi = 0; mi < 4; mi++)
#pragma unroll
                for (int ni = 0; ni < 2; ni++)
                    wmma::mma_sync(acc[mi][ni], af[mi], bf2[ni], acc[mi][ni]);
        }
        if (kt < 31) computeA(kt + 1, buf ^ 1);
    }
    __syncthreads();

    // epilogue: tile -> smem, bias+relu, contract with cw3 chunk
#pragma unroll
    for (int mi = 0; mi < 4; mi++)
#pragma unroll
        for (int ni = 0; ni < 2; ni++)
            wmma::store_matrix_sync(Cs + (wm * 64 + mi * 16) * C_LD + wn * 32 + ni * 16,
                                    acc[mi][ni], C_LD, wmma::mem_row_major);
    __syncthreads();

    if (tid < 128) {
        int r = tid;
        const float* cr = Cs + r * C_LD;
        float s0 = 0.f, s1 = 0.f, s2 = 0.f;
#pragma unroll 4
        for (int c = 0; c < 128; c++) {
            float x = fmaxf(cr[c] + s_bias2[c], 0.f);
            s0 = fmaf(x, s_cw3[0][c], s0);
            s1 = fmaf(x, s_cw3[1][c], s1);
            s2 = fmaf(x, s_cw3[2][c], s2);
        }
        size_t rg = (size_t)row0 + r;
        finepart[((size_t)bx * RT + rg) * 3 + 0] = s0;
        finepart[((size_t)bx * RT + rg) * 3 + 1] = s1;
        finepart[((size_t)bx * RT + rg) * 3 + 2] = s2;
    }
}

// ---------------- reduce fine partials (fixed order -> deterministic) ----------------
__global__ void finered_kernel(const float* __restrict__ cb3) {
    int row = blockIdx.x * 256 + threadIdx.x;     // RT total
    float s0 = cb3[0], s1 = cb3[1], s2 = cb3[2];
#pragma unroll
    for (int bx = 0; bx < 8; bx++) {
        const float* fp = d_finepart + ((size_t)bx * RT + row) * 3;
        s0 += fp[0]; s1 += fp[1]; s2 += fp[2];
    }
    int p = row >> 6, k = row & 63;
    const float* cp = d_coarse + p * 48 + (k >> 2) * 3;
    d_fine[row * 3 + 0] = s0 + cp[0];
    d_fine[row * 3 + 1] = s1 + cp[1];
    d_fine[row * 3 + 2] = s2 + cp[2];
}

// ---------------- Chamfer per patch ----------------
__global__ void chamfer_kernel() {
    int pt = blockIdx.x;          // 2048
    int t = threadIdx.x;          // 64
    __shared__ float F[64][3], G[64][3];
    const float* fr = d_fine + (size_t)pt * 64 * 3;
    const float* gr = d_gxyz + (size_t)pt * 64 * 3;
    for (int i = t; i < 192; i += 64) {
        ((float*)F)[i] = fr[i];
        ((float*)G)[i] = gr[i];
    }
    __syncthreads();
    float fx = F[t][0], fy = F[t][1], fz = F[t][2];
    float gx = G[t][0], gy = G[t][1], gz = G[t][2];
    float rmin = 1e30f, cmin = 1e30f;
#pragma unroll 4
    for (int s = 0; s < 64; s++) {
        float dx = fx - G[s][0], dy = fy - G[s][1], dz = fz - G[s][2];
        rmin = fminf(rmin, dx * dx + dy * dy + dz * dz);
        float ex = F[s][0] - gx, ey = F[s][1] - gy, ez = F[s][2] - gz;
        cmin = fminf(cmin, ex * ex + ey * ey + ez * ez);
    }
    float v = rmin + cmin;
#pragma unroll
    for (int off = 16; off; off >>= 1) v += __shfl_down_sync(0xffffffffu, v, off);
    __shared__ float ws[2];
    if ((t & 31) == 0) ws[t >> 5] = v;
    __syncthreads();
    if (t == 0) d_partial[pt] = ws[0] + ws[1];
}

// ---------------- deterministic final reduction ----------------
__global__ void final_kernel(float* __restrict__ out) {
    __shared__ float s[256];
    int t = threadIdx.x;
    float a = 0.f;
    for (int i = t; i < BP; i += 256) a += d_partial[i];
    s[t] = a;
    __syncthreads();
    for (int o = 128; o; o >>= 1) {
        if (t < o) s[t] += s[t + o];
        __syncthreads();
    }
    if (t == 0) out[0] = s[0] * (1.0f / 131072.0f);
}

// ---------------- launch ----------------
extern "C" void kernel_launch(void* const* d_in, const int* in_sizes, int n_in,
                              void* d_out, int out_size) {
    const float* xyz = (const float*)d_in[0];
    const float* feat = (const float*)d_in[1];
    const float* w1 = (const float*)d_in[2];  const float* b1 = (const float*)d_in[3];
    const float* w2 = (const float*)d_in[4];  const float* b2 = (const float*)d_in[5];
    const float* w3 = (const float*)d_in[6];  const float* b3 = (const float*)d_in[7];
    const float* cw1 = (const float*)d_in[8]; const float* cb1 = (const float*)d_in[9];
    const float* g1 = (const float*)d_in[10]; const float* be1 = (const float*)d_in[11];
    const float* m1 = (const float*)d_in[12]; const float* v1 = (const float*)d_in[13];
    const float* cw2 = (const float*)d_in[14]; const float* cb2 = (const float*)d_in[15];
    const float* g2 = (const float*)d_in[16]; const float* be2 = (const float*)d_in[17];
    const float* m2 = (const float*)d_in[18]; const float* v2 = (const float*)d_in[19];
    const float* cw3 = (const float*)d_in[20]; const float* cb3 = (const float*)d_in[21];

    float *p_pf, *p_ha, *p_hb, *p_base1, *p_fp;
    cudaGetSymbolAddress((void**)&p_pf, d_pf);
    cudaGetSymbolAddress((void**)&p_ha, d_ha);
    cudaGetSymbolAddress((void**)&p_hb, d_hb);
    cudaGetSymbolAddress((void**)&p_base1, d_base1);
    cudaGetSymbolAddress((void**)&p_fp, d_finepart);

    cudaFuncSetAttribute(conv2_fused_kernel,
                         cudaFuncAttributeMaxDynamicSharedMemorySize, DYN_BYTES);

    fps_kernel<<<Bb, 256>>>(xyz);
    topk_kernel<<<BP, 256>>>(xyz);
    pfeat_kernel<<<BP, 128>>>(feat);

    // FoldingNet MLP on patch features
    sgemm_kernel<<<dim3(8, 16), 256>>>(p_pf, w1, b1, p_ha, BP, DFF, Dd, 1);
    sgemm_kernel<<<dim3(8, 16), 256>>>(p_ha, w2, b2, p_hb, BP, DFF, DFF, 1);
    mlp3_kernel<<<BP, 128>>>(w3, b3);

    // conv1 patch-level part (base1 = pf@cw1[:128]+cb1) + bf16 weight prescale
    sgemm_kernel<<<dim3(8, 16), 256>>>(p_pf, cw1, cb1, p_base1, BP, DFF, Dd, 0);
    prescale_kernel<<<DFF * DFF / 256, 256>>>(cw2, g2, v2);

    // fused conv1+conv2 on bf16 tensor cores, BN+relu+conv3 epilogue
    conv2_fused_kernel<<<dim3(8, 1024), 256, DYN_BYTES>>>(
        p_base1, cw1, g1, be1, m1, v1, cb2, g2, be2, m2, v2, cw3, p_fp);

    finered_kernel<<<RT / 256, 256>>>(cb3);
    chamfer_kernel<<<BP, 64>>>();
    final_kernel<<<1, 256>>>((float*)d_out);
}

// round 9
// speedup vs baseline: 3.8804x; 1.0413x over previous
#include <cuda_runtime.h>
#include <cuda_bf16.h>
#include <mma.h>
#include <math.h>
#include <stdint.h>
#include <stddef.h>

using namespace nvcuda;

#define Bb   8
#define Nn   4096
#define Dd   128
#define Pp   256
#define Kk   64
#define DFF  1024
#define BP   2048          // B*P patches
#define RT   131072        // BP*Kk point rows
#define EPSB 1e-5f

// ---------------- scratch (static device memory; no allocations) ----------------
__device__ int   d_fidx[BP];
__device__ int   d_gidx[RT];
__device__ float d_gxyz[RT * 3];
__device__ float d_pf[BP * Dd];
__device__ float d_ha[BP * DFF];
__device__ float d_hb[BP * DFF];
__device__ float d_coarse[BP * 48];
__device__ float d_base1[BP * DFF];
__device__ __nv_bfloat16 d_cw2b[DFF * DFF];           // BN-scaled bf16 cw2 [k][n] (2 MB)
__device__ __nv_bfloat16 d_h1b[(size_t)RT * DFF];     // bf16 h1 (256 MB)
__device__ float d_fine[RT * 3];
__device__ float d_partial[BP];

// ---------------- helpers ----------------
__device__ __forceinline__ unsigned int sptr(const void* p) {
    unsigned int a;
    asm("{ .reg .u64 t; cvta.to.shared.u64 t, %1; cvt.u32.u64 %0, t; }"
        : "=r"(a) : "l"(p));
    return a;
}
__device__ __forceinline__ void cpa16(unsigned int dst, const void* src) {
    asm volatile("cp.async.cg.shared.global [%0], [%1], 16;" :: "r"(dst), "l"(src));
}
__device__ __forceinline__ void cpcommit() {
    asm volatile("cp.async.commit_group;");
}

// ---------------- FPS: one block per batch, sequential 255 argmax steps ----------------
__global__ void fps_kernel(const float* __restrict__ xyz) {
    int b = blockIdx.x;
    const float* X = xyz + (size_t)b * Nn * 3;
    int t = threadIdx.x;  // 256 threads, 16 points each (strided)

    float px[16], py[16], pz[16], md[16];
#pragma unroll
    for (int i = 0; i < 16; i++) {
        int n = i * 256 + t;
        px[i] = X[n * 3 + 0]; py[i] = X[n * 3 + 1]; pz[i] = X[n * 3 + 2];
        md[i] = 1e10f;
    }
    __shared__ float scx, scy, scz;
    __shared__ float wv[8];
    __shared__ int   wi[8];
    if (t == 0) { d_fidx[b * Pp] = 0; scx = X[0]; scy = X[1]; scz = X[2]; }
    __syncthreads();

    for (int step = 1; step < Pp; step++) {
        float cx = scx, cy = scy, cz = scz;
        float bv = -1e30f; int bn = 0;
#pragma unroll
        for (int i = 0; i < 16; i++) {
            float dx = __fadd_rn(px[i], -cx);
            float dy = __fadd_rn(py[i], -cy);
            float dz = __fadd_rn(pz[i], -cz);
            float d  = __fadd_rn(__fadd_rn(__fmul_rn(dx, dx), __fmul_rn(dy, dy)),
                                 __fmul_rn(dz, dz));
            float m = fminf(md[i], d);
            md[i] = m;
            if (m > bv) { bv = m; bn = i * 256 + t; }
        }
#pragma unroll
        for (int off = 16; off; off >>= 1) {
            float ov = __shfl_down_sync(0xffffffffu, bv, off);
            int   on = __shfl_down_sync(0xffffffffu, bn, off);
            if (ov > bv || (ov == bv && on < bn)) { bv = ov; bn = on; }
        }
        if ((t & 31) == 0) { wv[t >> 5] = bv; wi[t >> 5] = bn; }
        __syncthreads();
        if (t == 0) {
            float fv = wv[0]; int fn = wi[0];
#pragma unroll
            for (int w = 1; w < 8; w++)
                if (wv[w] > fv || (wv[w] == fv && wi[w] < fn)) { fv = wv[w]; fn = wi[w]; }
            d_fidx[b * Pp + step] = fn;
            scx = X[fn * 3 + 0]; scy = X[fn * 3 + 1]; scz = X[fn * 3 + 2];
        }
        __syncthreads();
    }
}

// ---------------- top-K (64 nearest of 4096) per patch + grouped_xyz_norm ----------------
__global__ void topk_kernel(const float* __restrict__ xyz) {
    int pp = blockIdx.x;          // 0..2047
    int b  = pp >> 8;
    const float* X = xyz + (size_t)b * Nn * 3;
    int t = threadIdx.x;          // 256

    __shared__ float sd[16 * 256];
    __shared__ float wv[8];
    __shared__ int   wi[8];
    __shared__ int   sel;

    int cI = d_fidx[pp];
    float cx = X[cI * 3 + 0], cy = X[cI * 3 + 1], cz = X[cI * 3 + 2];

    float mv = 1e30f; int mn = 0x7fffffff;
#pragma unroll
    for (int i = 0; i < 16; i++) {
        int n = i * 256 + t;
        float dx = X[n * 3 + 0] - cx, dy = X[n * 3 + 1] - cy, dz = X[n * 3 + 2] - cz;
        float d = dx * dx + dy * dy + dz * dz;
        sd[i * 256 + t] = d;
        if (d < mv) { mv = d; mn = n; }
    }

    for (int k = 0; k < Kk; k++) {
        float v = mv; int n = mn;
#pragma unroll
        for (int off = 16; off; off >>= 1) {
            float ov = __shfl_down_sync(0xffffffffu, v, off);
            int   on = __shfl_down_sync(0xffffffffu, n, off);
            if (ov < v || (ov == v && on < n)) { v = ov; n = on; }
        }
        if ((t & 31) == 0) { wv[t >> 5] = v; wi[t >> 5] = n; }
        __syncthreads();
        if (t == 0) {
            float fv = wv[0]; int fn = wi[0];
#pragma unroll
            for (int w = 1; w < 8; w++)
                if (wv[w] < fv || (wv[w] == fv && wi[w] < fn)) { fv = wv[w]; fn = wi[w]; }
            sel = fn;
            d_gidx[pp * Kk + k] = fn;
            d_gxyz[(pp * Kk + k) * 3 + 0] = X[fn * 3 + 0] - cx;
            d_gxyz[(pp * Kk + k) * 3 + 1] = X[fn * 3 + 1] - cy;
            d_gxyz[(pp * Kk + k) * 3 + 2] = X[fn * 3 + 2] - cz;
        }
        __syncthreads();
        int s = sel;
        if ((s & 255) == t) {
            sd[(s >> 8) * 256 + t] = 1e30f;
            mv = 1e30f; mn = 0x7fffffff;
#pragma unroll
            for (int i = 0; i < 16; i++) {
                float d = sd[i * 256 + t];
                if (d < mv) { mv = d; mn = i * 256 + t; }
            }
        }
    }
}

// ---------------- patch feature: max over K neighbors ----------------
__global__ void pfeat_kernel(const float* __restrict__ feat) {
    int pp = blockIdx.x;          // 2048
    int b  = pp >> 8;
    int dch = threadIdx.x;        // 128
    const float* F = feat + (size_t)b * Nn * Dd;
    float mx = -1e30f;
#pragma unroll 4
    for (int k = 0; k < Kk; k++) {
        int n = d_gidx[pp * Kk + k];
        mx = fmaxf(mx, F[(size_t)n * Dd + dch]);
    }
    d_pf[pp * Dd + dch] = mx;
}

// ---------------- generic fp32 SGEMM 128x128x8 (small GEMMs only) ----------------
// mode 0: +bias ; mode 1: +bias, relu
__global__ __launch_bounds__(256) void sgemm_kernel(
    const float* __restrict__ A, const float* __restrict__ B, const float* __restrict__ bias,
    float* __restrict__ C, int M, int N, int K, int mode)
{
    __shared__ float As[8][128];
    __shared__ float Bs[8][128];
    int tid = threadIdx.x;
    int bx = blockIdx.x, by = blockIdx.y;
    int tx = tid & 15, ty = tid >> 4;
    int row0 = by * 128, col0 = bx * 128;
    int ar = tid >> 1, ac = (tid & 1) * 4;
    int br = tid >> 5, bc = (tid & 31) * 4;
    const float* Ap = A + (size_t)(row0 + ar) * K + ac;
    const float* Bp = B + (size_t)br * N + col0 + bc;

    float acc[8][8];
#pragma unroll
    for (int i = 0; i < 8; i++)
#pragma unroll
        for (int j = 0; j < 8; j++) acc[i][j] = 0.f;

    for (int kt = 0; kt < K; kt += 8) {
        float4 a4 = *(const float4*)(Ap + kt);
        float4 b4 = *(const float4*)(Bp + (size_t)kt * N);
        __syncthreads();
        As[ac + 0][ar] = a4.x; As[ac + 1][ar] = a4.y;
        As[ac + 2][ar] = a4.z; As[ac + 3][ar] = a4.w;
        *(float4*)(&Bs[br][bc]) = b4;
        __syncthreads();
#pragma unroll
        for (int k = 0; k < 8; k++) {
            float a[8], bfr[8];
#pragma unroll
            for (int i = 0; i < 8; i++) a[i] = As[k][ty * 8 + i];
#pragma unroll
            for (int j = 0; j < 8; j++) bfr[j] = Bs[k][tx * 8 + j];
#pragma unroll
            for (int i = 0; i < 8; i++)
#pragma unroll
                for (int j = 0; j < 8; j++) acc[i][j] = fmaf(a[i], bfr[j], acc[i][j]);
        }
    }

#pragma unroll
    for (int j = 0; j < 8; j++) {
        int c = col0 + tx * 8 + j;
        float tb = bias[c];
#pragma unroll
        for (int i = 0; i < 8; i++) {
            int r = row0 + ty * 8 + i;
            float x = acc[i][j] + tb;
            if (mode >= 1) x = fmaxf(x, 0.f);
            C[(size_t)r * N + c] = x;
        }
    }
}

// ---------------- MLP layer 3 (N=48): coarse = hb @ w3 + b3 ----------------
__global__ void mlp3_kernel(const float* __restrict__ w3, const float* __restrict__ b3) {
    int row = blockIdx.x;         // 2048
    __shared__ float a[1024];
    int t = threadIdx.x;          // 128
    for (int i = t; i < 1024; i += 128) a[i] = d_hb[(size_t)row * 1024 + i];
    __syncthreads();
    if (t < 48) {
        float s0 = 0.f, s1 = 0.f, s2 = 0.f, s3 = 0.f;
#pragma unroll 4
        for (int k = 0; k < 1024; k += 4) {
            s0 = fmaf(a[k + 0], w3[(k + 0) * 48 + t], s0);
            s1 = fmaf(a[k + 1], w3[(k + 1) * 48 + t], s1);
            s2 = fmaf(a[k + 2], w3[(k + 2) * 48 + t], s2);
            s3 = fmaf(a[k + 3], w3[(k + 3) * 48 + t], s3);
        }
        d_coarse[row * 48 + t] = ((s0 + s1) + (s2 + s3)) + b3[t];
    }
}

// ---------------- prescale cw2 by BN scale, convert to bf16 [k][n] ----------------
__global__ void prescale_kernel(const float* __restrict__ cw2,
                                const float* __restrict__ g2,
                                const float* __restrict__ v2) {
    int idx = blockIdx.x * 256 + threadIdx.x;   // 1M total
    int c = idx & 1023;
    float sc = g2[c] * rsqrtf(v2[c] + EPSB);
    d_cw2b[idx] = __float2bfloat16(cw2[idx] * sc);
}

// ---------------- conv layer 1 -> bf16 h1: relu(bn(base1 + seed/pts rank-1 terms)) ----------------
__global__ void conv1h_kernel(const float* __restrict__ cw1, const float* __restrict__ g1,
                              const float* __restrict__ be1, const float* __restrict__ m1,
                              const float* __restrict__ v1) {
    int p = blockIdx.x;           // 2048 patches
    int t = threadIdx.x;          // 256
    float bs[4], c0[4], c1[4], c2[4], c3[4], c4[4], sc[4], tr[4];
#pragma unroll
    for (int q = 0; q < 4; q++) {
        int j = t + q * 256;
        bs[q] = d_base1[p * 1024 + j];
        c0[q] = cw1[128 * 1024 + j];
        c1[q] = cw1[129 * 1024 + j];
        c2[q] = cw1[130 * 1024 + j];
        c3[q] = cw1[131 * 1024 + j];
        c4[q] = cw1[132 * 1024 + j];
        float s = g1[j] * rsqrtf(v1[j] + EPSB);
        sc[q] = s;
        tr[q] = be1[j] - m1[j] * s;
    }
    for (int k = 0; k < 64; k++) {
        float sx = (k & 1) ? 0.05f : -0.05f;
        float sy = (k & 2) ? 0.05f : -0.05f;
        const float* cp = d_coarse + p * 48 + (k >> 2) * 3;
        float px = cp[0], py = cp[1], pz = cp[2];
        size_t rb = ((size_t)(p * 64 + k)) * 1024;
#pragma unroll
        for (int q = 0; q < 4; q++) {
            float tmp = bs[q] + sx * c0[q] + sy * c1[q] + px * c2[q] + py * c3[q] + pz * c4[q];
            d_h1b[rb + t + q * 256] =
                __float2bfloat16(fmaxf(fmaf(tmp, sc[q], tr[q]), 0.f));
        }
    }
}

// ================= conv2 bf16 GEMM: one block per 128-row band, loops 8 N-chunks =================
// A (h1b) stays L2-resident across chunks; cw3 contraction accumulated in registers -> d_fine.
#define AB_LD 40                  // bf16 elems per A row (32 + 8 pad)
#define BB_LD 136                 // bf16 elems per B row (128 + 8 pad)
#define A_TILE (128 * AB_LD)      // 5120 bf16
#define B_TILE (32 * BB_LD)       // 4352 bf16
#define C_LD   132
#define DYN_BYTES 67584           // max(2*(A_TILE+B_TILE)*2 = 37888, 128*C_LD*4 = 67584)

__global__ __launch_bounds__(256) void conv2_gemm_kernel(
    const float* __restrict__ cb2, const float* __restrict__ g2,
    const float* __restrict__ be2, const float* __restrict__ m2,
    const float* __restrict__ v2,  const float* __restrict__ cw3,
    const float* __restrict__ cb3)
{
    extern __shared__ char dynS[];
    __nv_bfloat16* As = (__nv_bfloat16*)dynS;                        // [2][128][AB_LD]
    __nv_bfloat16* Bs = (__nv_bfloat16*)(dynS + 2 * A_TILE * 2);     // [2][32][BB_LD]
    float* Cs = (float*)dynS;                                        // reuse: [128][C_LD]

    __shared__ float s_bias2[1024], s_w3x[1024], s_w3y[1024], s_w3z[1024];

    int tid = threadIdx.x;
    int wid = tid >> 5;
    int wm = wid >> 2;               // 0..1
    int wn = wid & 3;                // 0..3
    int by = blockIdx.x;             // row band 0..1023
    int row0 = by * 128;

    for (int c = tid; c < 1024; c += 256) {
        float sc = g2[c] * rsqrtf(v2[c] + EPSB);
        s_bias2[c] = (cb2[c] - m2[c]) * sc + be2[c];
        s_w3x[c] = cw3[c * 3 + 0];
        s_w3y[c] = cw3[c * 3 + 1];
        s_w3z[c] = cw3[c * 3 + 2];
    }
    __syncthreads();

    auto issueA = [&](int kt, int buf) {
#pragma unroll
        for (int s = 0; s < 2; s++) {
            int seg = tid + s * 256;       // 512 segs
            int row = seg >> 2;            // 0..127
            int part = (seg & 3) * 8;      // bf16 offset (4 x 16B per row)
            unsigned int dst = sptr(As + buf * A_TILE + row * AB_LD + part);
            const __nv_bfloat16* src =
                d_h1b + (size_t)(row0 + row) * 1024 + kt * 32 + part;
            cpa16(dst, src);
        }
    };
    auto issueB = [&](int nc, int kt, int buf) {
#pragma unroll
        for (int s = 0; s < 2; s++) {
            int seg = tid + s * 256;       // 512 segs
            int r = seg >> 4;              // 0..31 (k row)
            int cseg = (seg & 15) * 8;     // bf16 col offset
            unsigned int dst = sptr(Bs + buf * B_TILE + r * BB_LD + cseg);
            const __nv_bfloat16* src =
                d_cw2b + (size_t)(kt * 32 + r) * 1024 + nc * 128 + cseg;
            cpa16(dst, src);
        }
    };

    float fs0 = 0.f, fs1 = 0.f, fs2 = 0.f;      // fine accumulators (tid<128)

    for (int nc = 0; nc < 8; nc++) {
        wmma::fragment<wmma::accumulator, 16, 16, 16, float> acc[4][2];
#pragma unroll
        for (int mi = 0; mi < 4; mi++)
#pragma unroll
            for (int ni = 0; ni < 2; ni++) wmma::fill_fragment(acc[mi][ni], 0.f);

        issueA(0, 0); issueB(nc, 0, 0); cpcommit();

        for (int kt = 0; kt < 32; kt++) {
            int buf = kt & 1;
            asm volatile("cp.async.wait_group 0;");
            __syncthreads();
            if (kt < 31) { issueA(kt + 1, buf ^ 1); issueB(nc, kt + 1, buf ^ 1); cpcommit(); }

            const __nv_bfloat16* Ab = As + buf * A_TILE;
            const __nv_bfloat16* Bb2 = Bs + buf * B_TILE;
#pragma unroll
            for (int kk = 0; kk < 2; kk++) {
                wmma::fragment<wmma::matrix_a, 16, 16, 16, __nv_bfloat16, wmma::row_major> af[4];
                wmma::fragment<wmma::matrix_b, 16, 16, 16, __nv_bfloat16, wmma::row_major> bf2[2];
#pragma unroll
                for (int mi = 0; mi < 4; mi++)
                    wmma::load_matrix_sync(af[mi], Ab + (wm * 64 + mi * 16) * AB_LD + kk * 16, AB_LD);
#pragma unroll
                for (int ni = 0; ni < 2; ni++)
                    wmma::load_matrix_sync(bf2[ni], Bb2 + (kk * 16) * BB_LD + wn * 32 + ni * 16, BB_LD);
#pragma unroll
                for (int mi = 0; mi < 4; mi++)
#pragma unroll
                    for (int ni = 0; ni < 2; ni++)
                        wmma::mma_sync(acc[mi][ni], af[mi], bf2[ni], acc[mi][ni]);
            }
            __syncthreads();
        }

        // epilogue for this N chunk: tile -> smem, bias+relu, accumulate cw3 contraction
#pragma unroll
        for (int mi = 0; mi < 4; mi++)
#pragma unroll
            for (int ni = 0; ni < 2; ni++)
                wmma::store_matrix_sync(Cs + (wm * 64 + mi * 16) * C_LD + wn * 32 + ni * 16,
                                        acc[mi][ni], C_LD, wmma::mem_row_major);
        __syncthreads();

        if (tid < 128) {
            const float* cr = Cs + tid * C_LD;
            int cb = nc * 128;
#pragma unroll 4
            for (int c = 0; c < 128; c++) {
                float x = fmaxf(cr[c] + s_bias2[cb + c], 0.f);
                fs0 = fmaf(x, s_w3x[cb + c], fs0);
                fs1 = fmaf(x, s_w3y[cb + c], fs1);
                fs2 = fmaf(x, s_w3z[cb + c], fs2);
            }
        }
        __syncthreads();       // Cs region reused as A/B buffers next chunk
    }

    if (tid < 128) {
        int row = row0 + tid;
        int p = row >> 6, k = row & 63;
        const float* cp = d_coarse + p * 48 + (k >> 2) * 3;
        d_fine[row * 3 + 0] = fs0 + cb3[0] + cp[0];
        d_fine[row * 3 + 1] = fs1 + cb3[1] + cp[1];
        d_fine[row * 3 + 2] = fs2 + cb3[2] + cp[2];
    }
}

// ---------------- Chamfer per patch ----------------
__global__ void chamfer_kernel() {
    int pt = blockIdx.x;          // 2048
    int t = threadIdx.x;          // 64
    __shared__ float F[64][3], G[64][3];
    const float* fr = d_fine + (size_t)pt * 64 * 3;
    const float* gr = d_gxyz + (size_t)pt * 64 * 3;
    for (int i = t; i < 192; i += 64) {
        ((float*)F)[i] = fr[i];
        ((float*)G)[i] = gr[i];
    }
    __syncthreads();
    float fx = F[t][0], fy = F[t][1], fz = F[t][2];
    float gx = G[t][0], gy = G[t][1], gz = G[t][2];
    float rmin = 1e30f, cmin = 1e30f;
#pragma unroll 4
    for (int s = 0; s < 64; s++) {
        float dx = fx - G[s][0], dy = fy - G[s][1], dz = fz - G[s][2];
        rmin = fminf(rmin, dx * dx + dy * dy + dz * dz);
        float ex = F[s][0] - gx, ey = F[s][1] - gy, ez = F[s][2] - gz;
        cmin = fminf(cmin, ex * ex + ey * ey + ez * ez);
    }
    float v = rmin + cmin;
#pragma unroll
    for (int off = 16; off; off >>= 1) v += __shfl_down_sync(0xffffffffu, v, off);
    __shared__ float ws[2];
    if ((t & 31) == 0) ws[t >> 5] = v;
    __syncthreads();
    if (t == 0) d_partial[pt] = ws[0] + ws[1];
}

// ---------------- deterministic final reduction ----------------
__global__ void final_kernel(float* __restrict__ out) {
    __shared__ float s[256];
    int t = threadIdx.x;
    float a = 0.f;
    for (int i = t; i < BP; i += 256) a += d_partial[i];
    s[t] = a;
    __syncthreads();
    for (int o = 128; o; o >>= 1) {
        if (t < o) s[t] += s[t + o];
        __syncthreads();
    }
    if (t == 0) out[0] = s[0] * (1.0f / 131072.0f);
}

// ---------------- launch ----------------
extern "C" void kernel_launch(void* const* d_in, const int* in_sizes, int n_in,
                              void* d_out, int out_size) {
    const float* xyz = (const float*)d_in[0];
    const float* feat = (const float*)d_in[1];
    const float* w1 = (const float*)d_in[2];  const float* b1 = (const float*)d_in[3];
    const float* w2 = (const float*)d_in[4];  const float* b2 = (const float*)d_in[5];
    const float* w3 = (const float*)d_in[6];  const float* b3 = (const float*)d_in[7];
    const float* cw1 = (const float*)d_in[8]; const float* cb1 = (const float*)d_in[9];
    const float* g1 = (const float*)d_in[10]; const float* be1 = (const float*)d_in[11];
    const float* m1 = (const float*)d_in[12]; const float* v1 = (const float*)d_in[13];
    const float* cw2 = (const float*)d_in[14]; const float* cb2 = (const float*)d_in[15];
    const float* g2 = (const float*)d_in[16]; const float* be2 = (const float*)d_in[17];
    const float* m2 = (const float*)d_in[18]; const float* v2 = (const float*)d_in[19];
    const float* cw3 = (const float*)d_in[20]; const float* cb3 = (const float*)d_in[21];

    float *p_pf, *p_ha, *p_hb, *p_base1;
    cudaGetSymbolAddress((void**)&p_pf, d_pf);
    cudaGetSymbolAddress((void**)&p_ha, d_ha);
    cudaGetSymbolAddress((void**)&p_hb, d_hb);
    cudaGetSymbolAddress((void**)&p_base1, d_base1);

    cudaFuncSetAttribute(conv2_gemm_kernel,
                         cudaFuncAttributeMaxDynamicSharedMemorySize, DYN_BYTES);

    fps_kernel<<<Bb, 256>>>(xyz);
    topk_kernel<<<BP, 256>>>(xyz);
    pfeat_kernel<<<BP, 128>>>(feat);

    // FoldingNet MLP on patch features
    sgemm_kernel<<<dim3(8, 16), 256>>>(p_pf, w1, b1, p_ha, BP, DFF, Dd, 1);
    sgemm_kernel<<<dim3(8, 16), 256>>>(p_ha, w2, b2, p_hb, BP, DFF, DFF, 1);
    mlp3_kernel<<<BP, 128>>>(w3, b3);

    // conv1 patch-level part (base1 = pf@cw1[:128]+cb1), weight prescale, bf16 h1
    sgemm_kernel<<<dim3(8, 16), 256>>>(p_pf, cw1, cb1, p_base1, BP, DFF, Dd, 0);
    prescale_kernel<<<DFF * DFF / 256, 256>>>(cw2, g2, v2);
    conv1h_kernel<<<BP, 256>>>(cw1, g1, be1, m1, v1);

    // conv2 pure bf16 GEMM, fused BN+relu+conv3, fine written directly
    conv2_gemm_kernel<<<1024, 256, DYN_BYTES>>>(cb2, g2, be2, m2, v2, cw3, cb3);

    chamfer_kernel<<<BP, 64>>>();
    final_kernel<<<1, 256>>>((float*)d_out);
}